// round 2
// baseline (speedup 1.0000x reference)
#include <cuda_runtime.h>
#include <cuda_bf16.h>
#include <cstdint>
#include <cstddef>

#define QL      64
#define BSZ     8
#define CACHE_L 64
#define CACHE_N 512
#define NHID    1024
#define TOPK    4

#define NPAIRS    (CACHE_N / 2)          // 256 CTAs in x, one per 2 cache slots
#define ATT_ELEMS (QL * BSZ * CACHE_N)   // 262144
#define IDX_ELEMS (TOPK * QL * BSZ)      // 2048

// Q hi/lo bf16 scratch, layout [b][i][h]
__device__ __align__(16) __nv_bfloat16 g_qh[BSZ * QL * NHID];
__device__ __align__(16) __nv_bfloat16 g_ql[BSZ * QL * NHID];

// ---------------------------------------------------------------------------
__device__ __forceinline__ uint32_t smem_u32(const void* p) {
    uint32_t a;
    asm("{ .reg .u64 t; cvta.to.shared.u64 t, %1; cvt.u32.u64 %0, t; }"
        : "=r"(a) : "l"(p));
    return a;
}

__device__ __forceinline__ uint32_t sw128(uint32_t o) {
    return o ^ ((o >> 3) & 0x70);
}

__device__ __forceinline__ void cp_async16(uint32_t dst, const void* src) {
    asm volatile("cp.async.cg.shared.global [%0], [%1], 16;"
                 :: "r"(dst), "l"(src) : "memory");
}
__device__ __forceinline__ void cp_commit() {
    asm volatile("cp.async.commit_group;" ::: "memory");
}
template <int N>
__device__ __forceinline__ void cp_wait() {
    asm volatile("cp.async.wait_group %0;" :: "n"(N) : "memory");
}

__device__ __forceinline__ void ldm_x4(uint32_t& r0, uint32_t& r1,
                                       uint32_t& r2, uint32_t& r3, uint32_t a) {
    asm volatile("ldmatrix.sync.aligned.m8n8.x4.shared.b16 {%0,%1,%2,%3}, [%4];"
                 : "=r"(r0), "=r"(r1), "=r"(r2), "=r"(r3) : "r"(a));
}

__device__ __forceinline__ void mma16816(float* c, const uint32_t* a,
                                         const uint32_t* b) {
    asm volatile(
        "mma.sync.aligned.m16n8k16.row.col.f32.bf16.bf16.f32 "
        "{%0,%1,%2,%3}, {%4,%5,%6,%7}, {%8,%9}, {%0,%1,%2,%3};"
        : "+f"(c[0]), "+f"(c[1]), "+f"(c[2]), "+f"(c[3])
        : "r"(a[0]), "r"(a[1]), "r"(a[2]), "r"(a[3]), "r"(b[0]), "r"(b[1]));
}

// ---------------------------------------------------------------------------
// Pass 0: split query fp32 -> (hi truncated bf16, lo round-nearest bf16)
// input layout: query[i, 0, b, h] ; output layout: [b][i][h]
// ---------------------------------------------------------------------------
__global__ void qprep_kernel(const float* __restrict__ query) {
    int idx = blockIdx.x * 256 + threadIdx.x;   // 0 .. 524287
    float x = query[idx];
    uint32_t bx = __float_as_uint(x);
    float hi = __uint_as_float(bx & 0xffff0000u);  // truncated bf16 value
    float lo = x - hi;                              // exact residual
    int i  = idx >> 13;          // / (BSZ*NHID)
    int b  = (idx >> 10) & 7;    // / NHID % BSZ
    int hh = idx & 1023;
    int o = (b * QL + i) * NHID + hh;
    g_qh[o] = __float2bfloat16_rz(x);
    g_ql[o] = __float2bfloat16_rn(lo);
}

// ---------------------------------------------------------------------------
// Pass 1: split-bf16 3-term GEMM (mma.sync) + max over tokens -> raw logits
//   per CTA: M=128 (2 slots x 64 tokens), N=64 (queries), K=1024
//   4 warps, each warp tile 32 x 64. A streamed global->regs; B via smem.
// ---------------------------------------------------------------------------
// dynamic smem: B buffers [2][2 halves][64 rows][128B swizzled] = 32 KB
#define BBUF_BYTES 16384
#define SMEM_TOTAL (2 * BBUF_BYTES)

__global__ void __launch_bounds__(128)
cache_gemm_kernel(const float* __restrict__ keys, float* __restrict__ out) {
    extern __shared__ char smem[];
    const uint32_t sB = smem_u32(smem);
    const int tid  = threadIdx.x;
    const int w    = tid >> 5;
    const int lane = tid & 31;
    const int b    = blockIdx.y;
    const int n0   = blockIdx.x * 2;

    // ---- per-lane A base: warp w owns rows [32w, 32w+32) of the 128-row tile
    const int slot = w >> 1;
    const int trow = ((w & 1) << 5) + (lane >> 2);   // token row for (mt=0,a0)
    const float* __restrict__ gA = keys
        + ((size_t)(n0 + slot) * BSZ + b) * (CACHE_L * NHID)
        + (size_t)trow * NHID + ((lane & 3) << 1);

    // ---- B staging (cp.async): thread t -> (row=t&63, half=t>>6), 128B/chunk
    const int brow  = tid & 63;
    const int bhalf = tid >> 6;
    const __nv_bfloat16* __restrict__ gB =
        (bhalf ? g_ql : g_qh) + ((size_t)b * QL + brow) * NHID;
    const uint32_t stsBase = sB + bhalf * 8192 + sw128((uint32_t)brow * 128);
    // swizzle of (row*128 + j*16): row*128 has bits>=7 only; j*16 bits 4..6.
    // sw128(row*128 + j*16) = sw128(row*128) ^ (j*16)  (XOR bits already applied)
    // (since ((off>>3)&0x70) depends only on bits 7..9 = row bits)

    // ---- ldmatrix per-lane address pieces
    const int lt     = lane >> 3;                 // tile 0..3
    const int lrow   = ((lt & 2) << 2) + (lane & 7); // row within 16-row pair
    const int lkoff  = (lt & 1) << 3;             // k offset 0 or 8

    // ---- accumulators
    float acc[2][8][4];
    #pragma unroll
    for (int mt = 0; mt < 2; mt++)
        #pragma unroll
        for (int nt = 0; nt < 8; nt++)
            #pragma unroll
            for (int c = 0; c < 4; c++) acc[mt][nt][c] = 0.0f;

    // ---- prologue: stage B chunk 0, preload A kstep 0
    {
        const __nv_bfloat16* s = gB;
        #pragma unroll
        for (int j = 0; j < 8; j++)
            cp_async16(stsBase ^ (j * 16), s + j * 8);
        cp_commit();
    }

    float2 cur[8], nxt[8];
    {
        const float* p = gA;
        #pragma unroll
        for (int mt = 0; mt < 2; mt++) {
            const float* q = p + mt * 16 * NHID;
            cur[mt * 4 + 0] = *(const float2*)(q);
            cur[mt * 4 + 1] = *(const float2*)(q + 8 * NHID);
            cur[mt * 4 + 2] = *(const float2*)(q + 8);
            cur[mt * 4 + 3] = *(const float2*)(q + 8 * NHID + 8);
        }
    }

    for (int kc = 0; kc < 16; kc++) {
        // stage next B chunk into the other buffer
        if (kc + 1 < 16) {
            const __nv_bfloat16* s = gB + (kc + 1) * 64;
            uint32_t d = stsBase + (((kc + 1) & 1) ? BBUF_BYTES : 0);
            #pragma unroll
            for (int j = 0; j < 8; j++)
                cp_async16(d ^ (j * 16), s + j * 8);
            cp_commit();
            cp_wait<1>();
        } else {
            cp_wait<0>();
        }
        __syncthreads();

        const uint32_t bufB = sB + ((kc & 1) ? BBUF_BYTES : 0);

        #pragma unroll
        for (int ks2 = 0; ks2 < 4; ks2++) {
            const int kstep = kc * 4 + ks2;

            // issue next A loads (global, fully sector-efficient)
            if (kstep < 63) {
                const float* p = gA + (kstep + 1) * 16;
                #pragma unroll
                for (int mt = 0; mt < 2; mt++) {
                    const float* q = p + mt * 16 * NHID;
                    nxt[mt * 4 + 0] = *(const float2*)(q);
                    nxt[mt * 4 + 1] = *(const float2*)(q + 8 * NHID);
                    nxt[mt * 4 + 2] = *(const float2*)(q + 8);
                    nxt[mt * 4 + 3] = *(const float2*)(q + 8 * NHID + 8);
                }
            }

            // convert cur -> ah/al fragments
            uint32_t ah[2][4], al[2][4];
            #pragma unroll
            for (int mt = 0; mt < 2; mt++) {
                #pragma unroll
                for (int j = 0; j < 4; j++) {
                    float2 v = cur[mt * 4 + j];
                    uint32_t bx = __float_as_uint(v.x);
                    uint32_t by = __float_as_uint(v.y);
                    ah[mt][j] = __byte_perm(bx, by, 0x7632);
                    float rx = v.x - __uint_as_float(bx & 0xffff0000u);
                    float ry = v.y - __uint_as_float(by & 0xffff0000u);
                    asm("cvt.rn.bf16x2.f32 %0, %1, %2;"
                        : "=r"(al[mt][j]) : "f"(ry), "f"(rx));
                }
            }

            // ldmatrix B fragments (hi and lo halves, 4 n-tile pairs each)
            uint32_t bh[8][2], bl[8][2];
            #pragma unroll
            for (int np = 0; np < 4; np++) {
                uint32_t off = (uint32_t)((16 * np + lrow) * 128
                                          + (ks2 * 16 + lkoff) * 2);
                uint32_t swo = sw128(off);
                ldm_x4(bh[2 * np][0], bh[2 * np][1],
                       bh[2 * np + 1][0], bh[2 * np + 1][1], bufB + swo);
                ldm_x4(bl[2 * np][0], bl[2 * np][1],
                       bl[2 * np + 1][0], bl[2 * np + 1][1],
                       bufB + 8192 + swo);
            }

            // 48 HMMA: Ah*Bh + Ah*Bl + Al*Bh
            #pragma unroll
            for (int mt = 0; mt < 2; mt++) {
                #pragma unroll
                for (int nt = 0; nt < 8; nt++) {
                    mma16816(acc[mt][nt], ah[mt], bh[nt]);
                    mma16816(acc[mt][nt], ah[mt], bl[nt]);
                    mma16816(acc[mt][nt], al[mt], bh[nt]);
                }
            }

            #pragma unroll
            for (int j = 0; j < 8; j++) cur[j] = nxt[j];
        }
        __syncthreads();   // protect B buffer before next-next stage overwrites
    }

    // ---- epilogue: max over token rows ----
    // lane holds: rows (i/4, i/4+8) x mt(+16), cols 8nt + 2(lane&3) + {0,1}
    float vmax[8][2];
    #pragma unroll
    for (int nt = 0; nt < 8; nt++) {
        float v0 = fmaxf(fmaxf(acc[0][nt][0], acc[0][nt][2]),
                         fmaxf(acc[1][nt][0], acc[1][nt][2]));
        float v1 = fmaxf(fmaxf(acc[0][nt][1], acc[0][nt][3]),
                         fmaxf(acc[1][nt][1], acc[1][nt][3]));
        #pragma unroll
        for (int o = 4; o < 32; o <<= 1) {
            v0 = fmaxf(v0, __shfl_xor_sync(0xffffffffu, v0, o));
            v1 = fmaxf(v1, __shfl_xor_sync(0xffffffffu, v1, o));
        }
        vmax[nt][0] = v0; vmax[nt][1] = v1;
    }

    float* sred = (float*)smem;   // 4 warps x 64 cols, overlaps B buf 0
    if (lane < 4) {
        #pragma unroll
        for (int nt = 0; nt < 8; nt++) {
            sred[w * 64 + 8 * nt + 2 * lane]     = vmax[nt][0];
            sred[w * 64 + 8 * nt + 2 * lane + 1] = vmax[nt][1];
        }
    }
    __syncthreads();

    {
        int i  = tid & 63;          // query index
        int sl = tid >> 6;          // slot within pair
        float v = fmaxf(sred[(sl * 2) * 64 + i], sred[(sl * 2 + 1) * 64 + i]);
        out[(size_t)i * (BSZ * CACHE_N) + (size_t)b * CACHE_N + n0 + sl] = v;
    }
}

// ---------------------------------------------------------------------------
// Pass 2: softmax over N=512 (scale 1/32) in-place + top-4 indices
// ---------------------------------------------------------------------------
__global__ void softmax_topk_kernel(float* __restrict__ out, int write_idx) {
    const int row = blockIdx.x;
    const int t   = threadIdx.x;   // 256
    float* p = out + (size_t)row * CACHE_N;

    __shared__ float vals[512];
    __shared__ float red[256];
    __shared__ int   redi[256];

    float x0 = p[t]       * 0.03125f;   // THETA / sqrt(NHID) = 1/32
    float x1 = p[t + 256] * 0.03125f;

    red[t] = fmaxf(x0, x1);
    __syncthreads();
    for (int s2 = 128; s2 > 0; s2 >>= 1) {
        if (t < s2) red[t] = fmaxf(red[t], red[t + s2]);
        __syncthreads();
    }
    float m = red[0];
    __syncthreads();

    float e0 = expf(x0 - m), e1 = expf(x1 - m);
    red[t] = e0 + e1;
    __syncthreads();
    for (int s2 = 128; s2 > 0; s2 >>= 1) {
        if (t < s2) red[t] += red[t + s2];
        __syncthreads();
    }
    float sum = red[0];

    float s0 = e0 / sum, s1 = e1 / sum;
    vals[t] = s0;  vals[t + 256] = s1;
    p[t] = s0;     p[t + 256] = s1;
    __syncthreads();

    if (write_idx) {
        float* oidx = out + ATT_ELEMS;
        for (int k = 0; k < TOPK; k++) {
            float v0 = vals[t], v1 = vals[t + 256];
            float bv; int bi2;
            if (v1 > v0) { bv = v1; bi2 = t + 256; }
            else         { bv = v0; bi2 = t; }
            red[t] = bv; redi[t] = bi2;
            __syncthreads();
            for (int s2 = 128; s2 > 0; s2 >>= 1) {
                if (t < s2) {
                    float ov = red[t + s2]; int oi = redi[t + s2];
                    if (ov > red[t] || (ov == red[t] && oi < redi[t])) {
                        red[t] = ov; redi[t] = oi;
                    }
                }
                __syncthreads();
            }
            if (t == 0) {
                oidx[k * (QL * BSZ) + row] = (float)redi[0];  // (k, ql, b)
                vals[redi[0]] = -1.0f;
            }
            __syncthreads();
        }
    }
}

// ---------------------------------------------------------------------------
extern "C" void kernel_launch(void* const* d_in, const int* in_sizes, int n_in,
                              void* d_out, int out_size) {
    const float* a0 = (const float*)d_in[0];
    const float* a1 = (const float*)d_in[1];
    const float* query = a0;
    const float* keys  = a1;
    if (in_sizes[0] != QL * BSZ * NHID) { query = a1; keys = a0; }

    float* out = (float*)d_out;

    qprep_kernel<<<(BSZ * QL * NHID) / 256, 256>>>(query);

    cache_gemm_kernel<<<dim3(NPAIRS, BSZ), 128, SMEM_TOTAL>>>(keys, out);

    int write_idx = (out_size >= ATT_ELEMS + IDX_ELEMS) ? 1 : 0;
    softmax_topk_kernel<<<QL * BSZ, 256>>>(out, write_idx);
}

// round 3
// speedup vs baseline: 1.2782x; 1.2782x over previous
#include <cuda_runtime.h>
#include <cuda_bf16.h>
#include <cstdint>
#include <cstddef>

#define QL      64
#define BSZ     8
#define CACHE_L 64
#define CACHE_N 512
#define NHID    1024
#define TOPK    4

#define NPAIRS    (CACHE_N / 2)
#define ATT_ELEMS (QL * BSZ * CACHE_N)   // 262144
#define IDX_ELEMS (TOPK * QL * BSZ)      // 2048

// Q hi/lo bf16 scratch, layout [b][i][h]
__device__ __align__(16) __nv_bfloat16 g_qh[BSZ * QL * NHID];
__device__ __align__(16) __nv_bfloat16 g_ql[BSZ * QL * NHID];

// ---------------------------------------------------------------------------
__device__ __forceinline__ uint32_t smem_u32(const void* p) {
    uint32_t a;
    asm("{ .reg .u64 t; cvta.to.shared.u64 t, %1; cvt.u32.u64 %0, t; }"
        : "=r"(a) : "l"(p));
    return a;
}

__device__ __forceinline__ void cp_async16(uint32_t dst, const void* src) {
    asm volatile("cp.async.cg.shared.global [%0], [%1], 16;"
                 :: "r"(dst), "l"(src) : "memory");
}
__device__ __forceinline__ void cp_commit() {
    asm volatile("cp.async.commit_group;" ::: "memory");
}
template <int N>
__device__ __forceinline__ void cp_wait() {
    asm volatile("cp.async.wait_group %0;" :: "n"(N) : "memory");
}

__device__ __forceinline__ void ldm_x4(uint32_t& r0, uint32_t& r1,
                                       uint32_t& r2, uint32_t& r3, uint32_t a) {
    asm volatile("ldmatrix.sync.aligned.m8n8.x4.shared.b16 {%0,%1,%2,%3}, [%4];"
                 : "=r"(r0), "=r"(r1), "=r"(r2), "=r"(r3) : "r"(a));
}

__device__ __forceinline__ void mma16816(float* c, const uint32_t* a,
                                         const uint32_t* b) {
    asm volatile(
        "mma.sync.aligned.m16n8k16.row.col.f32.bf16.bf16.f32 "
        "{%0,%1,%2,%3}, {%4,%5,%6,%7}, {%8,%9}, {%0,%1,%2,%3};"
        : "+f"(c[0]), "+f"(c[1]), "+f"(c[2]), "+f"(c[3])
        : "r"(a[0]), "r"(a[1]), "r"(a[2]), "r"(a[3]), "r"(b[0]), "r"(b[1]));
}

// ---------------------------------------------------------------------------
// Pass 0: split query fp32 -> (hi truncated bf16, lo round-nearest bf16)
// ---------------------------------------------------------------------------
__global__ void qprep_kernel(const float* __restrict__ query) {
    int idx = blockIdx.x * 256 + threadIdx.x;   // 0 .. 524287
    float x = query[idx];
    uint32_t bx = __float_as_uint(x);
    float hi = __uint_as_float(bx & 0xffff0000u);
    float lo = x - hi;
    int i  = idx >> 13;
    int b  = (idx >> 10) & 7;
    int hh = idx & 1023;
    int o = (b * QL + i) * NHID + hh;
    g_qh[o] = __float2bfloat16_rz(x);
    g_ql[o] = __float2bfloat16_rn(lo);
}

// ---------------------------------------------------------------------------
// Pass 1: split-bf16 3-term GEMM (mma.sync) + max over tokens -> raw logits
//   CTA: M=128 (2 slots x 64 tokens), N=64, K=1024 in 16 chunks of 64.
//   8 warps (4m x 2n), warp tile 32x32. A cp.async fp32 -> smem (2-stage),
//   converted to bf16 hi/lo in-register. B bf16 hi/lo cp.async (2-stage).
// ---------------------------------------------------------------------------
#define A_STAGE 32768                  // 128 rows x 256B (64 fp32)
#define B_STAGE 16384                  // hi 8KB + lo 8KB (64 rows x 128B)
#define B_BASE  (2 * A_STAGE)          // 65536
#define SMEM_TOTAL (B_BASE + 2 * B_STAGE)   // 98304

__global__ void __launch_bounds__(256, 2)
cache_gemm_kernel(const float* __restrict__ keys, float* __restrict__ out) {
    extern __shared__ char smem[];
    const uint32_t sbase = smem_u32(smem);
    const int tid  = threadIdx.x;
    const int w    = tid >> 5;
    const int lane = tid & 31;
    const int b    = blockIdx.y;
    const int n0   = blockIdx.x * 2;

    const int wm = w >> 1;             // m-block 0..3 (rows 32*wm ..)
    const int wn = w & 1;              // n-block 0..1 (cols 32*wn ..)

    // ---- A cp.async mapping: 8 granules of 16B per thread per chunk
    const int arow0 = tid >> 4;                   // 0..15
    const int akb   = (tid & 15) * 16;            // byte off in 256B row
    const float* srcA0 = keys
        + ((size_t)n0 * BSZ + b) * (CACHE_L * NHID)
        + (size_t)arow0 * NHID + (tid & 15) * 4;
    const uint32_t dstA0 = sbase + (uint32_t)(arow0 * 256
                         + (akb ^ ((arow0 & 7) << 5)));

    // ---- B cp.async mapping: 4 granules of 16B per thread per chunk
    const int bkb   = (tid & 7) * 16;             // byte off in 128B row
    const int brow0 = tid >> 3;                   // 0..31
    const size_t srcBoff = ((size_t)b * QL + brow0) * NHID + (tid & 7) * 8;

    // ---- ldmatrix per-lane pieces (B fragments)
    const int lt    = lane >> 3;
    const int lrow  = ((lt & 2) << 2) + (lane & 7);
    const int lkoff = (lt & 1) << 3;

    // ---- A fragment LDS pieces
    const int afr = (lane >> 2);       // row within 8-row group
    const int afk = (lane & 3) << 1;   // k pair index

    float acc[2][4][4];
    #pragma unroll
    for (int mt = 0; mt < 2; mt++)
        #pragma unroll
        for (int nt = 0; nt < 4; nt++)
            #pragma unroll
            for (int c = 0; c < 4; c++) acc[mt][nt][c] = 0.0f;

    // ---- prologue: stage chunks 0 and 1
    #pragma unroll 1
    for (int pk = 0; pk < 2; pk++) {
        uint32_t dA = dstA0 + pk * A_STAGE;
        const float* sA = srcA0 + pk * 64;
        #pragma unroll
        for (int j = 0; j < 8; j++) {
            const float* s = sA + j * 16 * NHID
                           + ((j >= 4) ? (7 * CACHE_L * NHID) : 0);
            cp_async16(dA + j * 4096, s);
        }
        uint32_t dBb = sbase + B_BASE + pk * B_STAGE;
        #pragma unroll
        for (int j = 0; j < 4; j++) {
            int half = j >> 1;
            int row  = brow0 + (j & 1) * 32;
            const __nv_bfloat16* s = (half ? g_ql : g_qh)
                + srcBoff + (size_t)(j & 1) * 32 * NHID + pk * 64;
            uint32_t d = dBb + half * 8192
                       + (uint32_t)(row * 128 + (bkb ^ ((row & 7) << 4)));
            cp_async16(d, s);
        }
        cp_commit();
    }

    #pragma unroll 1
    for (int kc = 0; kc < 16; kc++) {
        cp_wait<1>();
        __syncthreads();

        const uint32_t bufA = sbase + (kc & 1) * A_STAGE;
        const uint32_t bufB = sbase + B_BASE + (kc & 1) * B_STAGE;

        #pragma unroll
        for (int ks2 = 0; ks2 < 4; ks2++) {
            // ---- A fragments: LDS fp32, convert to bf16 hi/lo
            uint32_t ah[2][4], al[2][4];
            #pragma unroll
            for (int mt = 0; mt < 2; mt++) {
                const int R = wm * 32 + mt * 16 + afr;
                const int kidx = ks2 * 16 + afk;
                float2 v01, v23;
                // rows R, R+8 ; k kidx, kidx+8  (4 float2 loads)
                float2 f0 = *(const float2*)(smem + (kc & 1) * A_STAGE
                    + R * 256 + ((kidx * 4) ^ ((R & 7) << 5)));
                float2 f1 = *(const float2*)(smem + (kc & 1) * A_STAGE
                    + (R + 8) * 256 + ((kidx * 4) ^ (((R + 8) & 7) << 5)));
                float2 f2 = *(const float2*)(smem + (kc & 1) * A_STAGE
                    + R * 256 + (((kidx + 8) * 4) ^ ((R & 7) << 5)));
                float2 f3 = *(const float2*)(smem + (kc & 1) * A_STAGE
                    + (R + 8) * 256 + (((kidx + 8) * 4) ^ (((R + 8) & 7) << 5)));
                float2 fs[4] = {f0, f1, f2, f3};
                #pragma unroll
                for (int j = 0; j < 4; j++) {
                    uint32_t bx = __float_as_uint(fs[j].x);
                    uint32_t by = __float_as_uint(fs[j].y);
                    ah[mt][j] = __byte_perm(bx, by, 0x7632);
                    float rx = fs[j].x - __uint_as_float(bx & 0xffff0000u);
                    float ry = fs[j].y - __uint_as_float(by & 0xffff0000u);
                    asm("cvt.rn.bf16x2.f32 %0, %1, %2;"
                        : "=r"(al[mt][j]) : "f"(ry), "f"(rx));
                }
            }

            // ---- B fragments via ldmatrix (hi + lo)
            uint32_t bh[4][2], bl[4][2];
            #pragma unroll
            for (int np = 0; np < 2; np++) {
                int row = wn * 32 + 16 * np + lrow;
                uint32_t kb = (uint32_t)((ks2 * 16 + lkoff) * 2);
                uint32_t swo = (uint32_t)(row * 128 + (kb ^ ((row & 7) << 4)));
                ldm_x4(bh[2 * np][0], bh[2 * np][1],
                       bh[2 * np + 1][0], bh[2 * np + 1][1], bufB + swo);
                ldm_x4(bl[2 * np][0], bl[2 * np][1],
                       bl[2 * np + 1][0], bl[2 * np + 1][1],
                       bufB + 8192 + swo);
            }

            // ---- 24 HMMA: Ah*Bh + Ah*Bl + Al*Bh
            #pragma unroll
            for (int mt = 0; mt < 2; mt++) {
                #pragma unroll
                for (int nt = 0; nt < 4; nt++) {
                    mma16816(acc[mt][nt], ah[mt], bh[nt]);
                    mma16816(acc[mt][nt], ah[mt], bl[nt]);
                    mma16816(acc[mt][nt], al[mt], bh[nt]);
                }
            }
        }
        __syncthreads();

        // ---- stage chunk kc+2 into the buffer just freed
        if (kc + 2 < 16) {
            uint32_t dA = dstA0 + (kc & 1) * A_STAGE;
            const float* sA = srcA0 + (kc + 2) * 64;
            #pragma unroll
            for (int j = 0; j < 8; j++) {
                const float* s = sA + j * 16 * NHID
                               + ((j >= 4) ? (7 * CACHE_L * NHID) : 0);
                cp_async16(dA + j * 4096, s);
            }
            uint32_t dBb = sbase + B_BASE + (kc & 1) * B_STAGE;
            #pragma unroll
            for (int j = 0; j < 4; j++) {
                int half = j >> 1;
                int row  = brow0 + (j & 1) * 32;
                const __nv_bfloat16* s = (half ? g_ql : g_qh)
                    + srcBoff + (size_t)(j & 1) * 32 * NHID + (kc + 2) * 64;
                uint32_t d = dBb + half * 8192
                           + (uint32_t)(row * 128 + (bkb ^ ((row & 7) << 4)));
                cp_async16(d, s);
            }
        }
        cp_commit();   // unconditional: keeps group accounting uniform
    }

    // ---- epilogue: max over token rows ----
    float vmax[4][2];
    #pragma unroll
    for (int nt = 0; nt < 4; nt++) {
        float v0 = fmaxf(fmaxf(acc[0][nt][0], acc[0][nt][2]),
                         fmaxf(acc[1][nt][0], acc[1][nt][2]));
        float v1 = fmaxf(fmaxf(acc[0][nt][1], acc[0][nt][3]),
                         fmaxf(acc[1][nt][1], acc[1][nt][3]));
        #pragma unroll
        for (int o = 4; o < 32; o <<= 1) {
            v0 = fmaxf(v0, __shfl_xor_sync(0xffffffffu, v0, o));
            v1 = fmaxf(v1, __shfl_xor_sync(0xffffffffu, v1, o));
        }
        vmax[nt][0] = v0; vmax[nt][1] = v1;
    }

    float* sred = (float*)smem;   // 8 warps x 32 cols
    if (lane < 4) {
        #pragma unroll
        for (int nt = 0; nt < 4; nt++) {
            sred[w * 32 + 8 * nt + 2 * lane]     = vmax[nt][0];
            sred[w * 32 + 8 * nt + 2 * lane + 1] = vmax[nt][1];
        }
    }
    __syncthreads();

    if (tid < 128) {
        int i  = tid & 63;          // query index
        int sl = tid >> 6;          // slot within pair (rows 0-63 / 64-127)
        int cn = i >> 5;            // wn group
        int c  = i & 31;
        float v = fmaxf(sred[((sl * 2 + 0) * 2 + cn) * 32 + c],
                        sred[((sl * 2 + 1) * 2 + cn) * 32 + c]);
        out[(size_t)i * (BSZ * CACHE_N) + (size_t)b * CACHE_N + n0 + sl] = v;
    }
}

// ---------------------------------------------------------------------------
// Pass 2: softmax over N=512 (scale 1/32) in-place + top-4 indices
// ---------------------------------------------------------------------------
__global__ void softmax_topk_kernel(float* __restrict__ out, int write_idx) {
    const int row = blockIdx.x;
    const int t   = threadIdx.x;   // 256
    float* p = out + (size_t)row * CACHE_N;

    __shared__ float vals[512];
    __shared__ float red[256];
    __shared__ int   redi[256];

    float x0 = p[t]       * 0.03125f;
    float x1 = p[t + 256] * 0.03125f;

    red[t] = fmaxf(x0, x1);
    __syncthreads();
    for (int s2 = 128; s2 > 0; s2 >>= 1) {
        if (t < s2) red[t] = fmaxf(red[t], red[t + s2]);
        __syncthreads();
    }
    float m = red[0];
    __syncthreads();

    float e0 = expf(x0 - m), e1 = expf(x1 - m);
    red[t] = e0 + e1;
    __syncthreads();
    for (int s2 = 128; s2 > 0; s2 >>= 1) {
        if (t < s2) red[t] += red[t + s2];
        __syncthreads();
    }
    float sum = red[0];

    float s0 = e0 / sum, s1 = e1 / sum;
    vals[t] = s0;  vals[t + 256] = s1;
    p[t] = s0;     p[t + 256] = s1;
    __syncthreads();

    if (write_idx) {
        float* oidx = out + ATT_ELEMS;
        for (int k = 0; k < TOPK; k++) {
            float v0 = vals[t], v1 = vals[t + 256];
            float bv; int bi2;
            if (v1 > v0) { bv = v1; bi2 = t + 256; }
            else         { bv = v0; bi2 = t; }
            red[t] = bv; redi[t] = bi2;
            __syncthreads();
            for (int s2 = 128; s2 > 0; s2 >>= 1) {
                if (t < s2) {
                    float ov = red[t + s2]; int oi = redi[t + s2];
                    if (ov > red[t] || (ov == red[t] && oi < redi[t])) {
                        red[t] = ov; redi[t] = oi;
                    }
                }
                __syncthreads();
            }
            if (t == 0) {
                oidx[k * (QL * BSZ) + row] = (float)redi[0];  // (k, ql, b)
                vals[redi[0]] = -1.0f;
            }
            __syncthreads();
        }
    }
}

// ---------------------------------------------------------------------------
extern "C" void kernel_launch(void* const* d_in, const int* in_sizes, int n_in,
                              void* d_out, int out_size) {
    const float* a0 = (const float*)d_in[0];
    const float* a1 = (const float*)d_in[1];
    const float* query = a0;
    const float* keys  = a1;
    if (in_sizes[0] != QL * BSZ * NHID) { query = a1; keys = a0; }

    float* out = (float*)d_out;

    qprep_kernel<<<(BSZ * QL * NHID) / 256, 256>>>(query);

    cudaFuncSetAttribute(cache_gemm_kernel,
                         cudaFuncAttributeMaxDynamicSharedMemorySize, SMEM_TOTAL);
    cache_gemm_kernel<<<dim3(NPAIRS, BSZ), 256, SMEM_TOTAL>>>(keys, out);

    int write_idx = (out_size >= ATT_ELEMS + IDX_ELEMS) ? 1 : 0;
    softmax_topk_kernel<<<QL * BSZ, 256>>>(out, write_idx);
}